// round 9
// baseline (speedup 1.0000x reference)
#include <cuda_runtime.h>

#define S      256
#define C      5
#define SC     1280             // S*C floats per image row
#define B      64
#define SPLIT  8
#define TX     32
#define TY     32
#define VPITCH 171              // vertical-lerp span pitch (odd)
#define OPITCH 161              // out-staging pitch (odd)
#define GRAYW  (0.2989f + 0.5870f + 0.1140f)

// Per-(image,slab,channel) partial weighted sums. No device allocation allowed.
__device__ float g_part[B * SPLIT * C];

__device__ __forceinline__ void get_params(int b,
                                           const float* __restrict__ off_frac,
                                           const int* __restrict__ crop_size,
                                           const int* __restrict__ do_crop,
                                           bool& dc, float& scale, float& off0, float& off1) {
    dc = do_crop[b] != 0;
    float size_f = dc ? (float)crop_size[b] : (float)S;
    scale = size_f / (float)S;
    float span = (float)S - size_f + 1.0f;
    off0 = dc ? floorf(off_frac[2 * b + 0] * span) : 0.0f;
    off1 = dc ? floorf(off_frac[2 * b + 1] * span) : 0.0f;
}

__device__ __forceinline__ void inv_map(int k, bool fl, int y, int x, int& ry, int& rx) {
    switch (k) {
        case 0:  ry = y;         rx = x;         break;
        case 1:  ry = x;         rx = S - 1 - y; break;
        case 2:  ry = S - 1 - y; rx = S - 1 - x; break;
        default: ry = S - 1 - x; rx = y;         break;
    }
    if (fl) rx = S - 1 - rx;
}

// ---------------------------------------------------------------------------
// K1: per-(b,slab,c) partial weighted mean of the resampled image (~LTS cap).
// ---------------------------------------------------------------------------
__global__ __launch_bounds__(256) void mean_kernel(
    const float* __restrict__ img,
    const float* __restrict__ off_frac,
    const int* __restrict__ crop_size,
    const int* __restrict__ do_crop)
{
    __shared__ float W0[S];
    __shared__ float W1[S];
    __shared__ float red[8][C];

    const int b = blockIdx.x;
    const int slab = blockIdx.y;
    const int t = threadIdx.x;

    bool dc; float scale, off0, off1;
    get_params(b, off_frac, crop_size, do_crop, dc, scale, off0, off1);

    W0[t] = 0.0f;
    W1[t] = 0.0f;
    __syncthreads();

    {
        float base = ((float)t + 0.5f) * scale - 0.5f;

        float c0 = base + off0;
        float f0 = floorf(c0);
        int  i0 = min(max((int)f0, 0), S - 1);
        int  i1 = min(max((int)f0 + 1, 0), S - 1);
        float fy = c0 - f0;
        atomicAdd(&W0[i0], 1.0f - fy);
        atomicAdd(&W0[i1], fy);

        float c1 = base + off1;
        float f1 = floorf(c1);
        int  j0 = min(max((int)f1, 0), S - 1);
        int  j1 = min(max((int)f1 + 1, 0), S - 1);
        float fx = c1 - f1;
        atomicAdd(&W1[j0], 1.0f - fx);
        atomicAdd(&W1[j1], fx);
    }
    __syncthreads();

    const int g = t & 63;          // pixel group (4 px)
    const int r = t >> 6;          // row lane 0..3
    const int px0 = g * 4;
    float w1v0 = W1[px0], w1v1 = W1[px0 + 1], w1v2 = W1[px0 + 2], w1v3 = W1[px0 + 3];

    float acc[C] = {0.f, 0.f, 0.f, 0.f, 0.f};
    const int rows = S / SPLIT;
    const int row0 = slab * rows;
    const float* base = img + (size_t)b * S * SC;

    for (int it = 0; it < rows / 4; it++) {
        const int i = row0 + r + it * 4;
        const float w0 = W0[i];
        if (w0 == 0.0f) continue;
        const float4* p4 = (const float4*)(base + (size_t)i * SC + px0 * C);
        float4 v0 = p4[0], v1 = p4[1], v2 = p4[2], v3 = p4[3], v4 = p4[4];
        float ww0 = w0 * w1v0, ww1 = w0 * w1v1, ww2 = w0 * w1v2, ww3 = w0 * w1v3;
        acc[0] += v0.x * ww0; acc[1] += v0.y * ww0; acc[2] += v0.z * ww0; acc[3] += v0.w * ww0;
        acc[4] += v1.x * ww0;
        acc[0] += v1.y * ww1; acc[1] += v1.z * ww1; acc[2] += v1.w * ww1;
        acc[3] += v2.x * ww1; acc[4] += v2.y * ww1;
        acc[0] += v2.z * ww2; acc[1] += v2.w * ww2; acc[2] += v3.x * ww2;
        acc[3] += v3.y * ww2; acc[4] += v3.z * ww2;
        acc[0] += v3.w * ww3; acc[1] += v4.x * ww3; acc[2] += v4.y * ww3;
        acc[3] += v4.z * ww3; acc[4] += v4.w * ww3;
    }

#pragma unroll
    for (int c = 0; c < C; c++) {
        float v = acc[c];
#pragma unroll
        for (int o = 16; o > 0; o >>= 1)
            v += __shfl_down_sync(0xffffffffu, v, o);
        if ((t & 31) == 0) red[t >> 5][c] = v;
    }
    __syncthreads();

    if (t < C) {
        float s = 0.f;
#pragma unroll
        for (int w = 0; w < 8; w++) s += red[w][t];
        g_part[(b * SPLIT + slab) * C + t] = s;
    }
}

// ---------------------------------------------------------------------------
// K2: direct/separable gather, 4 block-uniform paths:
//  fast k-even : fully vectorized 4px/thread LDG.128 -> STG.128 (no smem)
//  fast k-odd  : warp-per-output-column gather -> OUT staging -> writeback
//  slow (crop) : separable bilinear: Phase V (dense vertical lerp into smem)
//                then Phase H (2-tap horizontal lerp + epilogue).
// Block = 32x32 tile; grid (8, 8, B); 256 threads.
// ---------------------------------------------------------------------------
__global__ __launch_bounds__(256) void aug_kernel(
    const float* __restrict__ img,
    const float* __restrict__ off_frac,
    const float* __restrict__ bright,
    const float* __restrict__ contrast,
    const int* __restrict__ crop_size,
    const int* __restrict__ do_crop,
    const int* __restrict__ flip,
    const int* __restrict__ rot_k,
    float* __restrict__ out)
{
    __shared__ float VR[TY * VPITCH];       // vertically-lerped spans
    __shared__ float OUTS[TY * OPITCH];     // staging for k-odd outputs
    __shared__ float Ash[C], Dsh[C];
    __shared__ int   ROWI0[32], ROWI1[32];  // absolute row offsets (i*SC)
    __shared__ float ROWF[32];
    __shared__ int   COLI0[32], COLI1[32];  // col float offsets (j*C)
    __shared__ float COLF[32];

    const int b  = blockIdx.z;
    const int x0 = blockIdx.x * TX;
    const int y0 = blockIdx.y * TY;
    const int t  = threadIdx.x;

    bool dc; float scale, off0, off1;
    get_params(b, off_frac, crop_size, do_crop, dc, scale, off0, off1);
    const int k = rot_k[b] & 3;
    const bool fl = flip[b] != 0;
    const int kodd = k & 1;

    // ---- per-axis tap tables ----
    if (t < 32) {                 // ROW: source-row taps (index: py if k even, px if k odd)
        int ry, rx;
        inv_map(k, fl, kodd ? y0 : y0 + t, kodd ? x0 + t : x0, ry, rx);
        float cy = ((float)ry + 0.5f) * scale - 0.5f + off0;
        float f = floorf(cy);
        ROWI0[t] = min(max((int)f, 0), S - 1) * SC;
        ROWI1[t] = min(max((int)f + 1, 0), S - 1) * SC;
        ROWF[t] = cy - f;
    } else if (t >= 64 && t < 96) { // COL: source-col taps (index: px if k even, py if k odd)
        int i = t - 64;
        int ry, rx;
        inv_map(k, fl, kodd ? y0 + i : y0, kodd ? x0 : x0 + i, ry, rx);
        float cx = ((float)rx + 0.5f) * scale - 0.5f + off1;
        float f = floorf(cx);
        COLI0[i] = min(max((int)f, 0), S - 1) * C;
        COLI1[i] = min(max((int)f + 1, 0), S - 1) * C;
        COLF[i] = cx - f;
    } else if (t >= 32 && t < 32 + C) {  // epilogue: o = v*A + D
        int c = t - 32;
        const float inv_area = 1.0f / (float)(S * S);
        float s = 0.f;
#pragma unroll
        for (int p = 0; p < SPLIT; p++) s += g_part[(b * SPLIT + p) * C + c];
        float m = s * inv_area;
        float cc = contrast[b * C + c];
        Ash[c] = cc * GRAYW;
        Dsh[c] = (m * (1.0f - cc) + bright[b * C + c]) * GRAYW;
    }
    __syncthreads();

    const float* imgb = img + (size_t)b * S * SC;
    float* outb = out + (size_t)b * S * SC;

    if (!dc) {
        if (!kodd) {
            // ---- fast, k even: 4 px/thread, fully vectorized ----
            const int py = t >> 3, g = t & 7;
            const bool rev = COLI0[1] < COLI0[0];
            const int jf = rev ? COLI0[g * 4 + 3] : COLI0[g * 4];   // 16B-aligned
            const float4* src = (const float4*)(imgb + ROWI0[py] + jf);
            float4 w0 = src[0], w1 = src[1], w2 = src[2], w3 = src[3], w4 = src[4];
            float v[20] = {w0.x, w0.y, w0.z, w0.w, w1.x, w1.y, w1.z, w1.w,
                           w2.x, w2.y, w2.z, w2.w, w3.x, w3.y, w3.z, w3.w,
                           w4.x, w4.y, w4.z, w4.w};
            float r[20];
            if (rev) {
#pragma unroll
                for (int p = 0; p < 4; p++)
#pragma unroll
                    for (int c = 0; c < C; c++)
                        r[p * C + c] = v[(3 - p) * C + c] * Ash[c] + Dsh[c];
            } else {
#pragma unroll
                for (int p = 0; p < 4; p++)
#pragma unroll
                    for (int c = 0; c < C; c++)
                        r[p * C + c] = v[p * C + c] * Ash[c] + Dsh[c];
            }
            float4* o = (float4*)(outb + (size_t)(y0 + py) * SC + (x0 + g * 4) * C);
            __stcs(o + 0, make_float4(r[0],  r[1],  r[2],  r[3]));
            __stcs(o + 1, make_float4(r[4],  r[5],  r[6],  r[7]));
            __stcs(o + 2, make_float4(r[8],  r[9],  r[10], r[11]));
            __stcs(o + 3, make_float4(r[12], r[13], r[14], r[15]));
            __stcs(o + 4, make_float4(r[16], r[17], r[18], r[19]));
            return;
        } else {
            // ---- fast, k odd: warp per output column, exact-pixel copy ----
            const int w = t >> 5, l = t & 31;
#pragma unroll
            for (int q = 0; q < 4; q++) {
                const int xl = w + q * 8;
                const float* s = imgb + ROWI0[xl] + COLI0[l];
                float* d = OUTS + l * OPITCH + xl * C;
#pragma unroll
                for (int c = 0; c < C; c++)
                    d[c] = s[c] * Ash[c] + Dsh[c];
            }
        }
    } else {
        const int lo = min(COLI0[0], COLI0[31]);
        const int hi = max(COLI1[0], COLI1[31]) + C;

        // ---- Phase V: dense vertical lerp of the needed span, warp per q ----
        {
            const int wid = t >> 5, lane = t & 31;
            for (int q = wid; q < 32; q += 8) {
                const float ty = ROWF[q];
                const float* r0 = imgb + ROWI0[q];
                const float* r1 = imgb + ROWI1[q];
                float* vq = VR + q * VPITCH - lo;
                for (int f = lo + lane; f < hi; f += 32) {
                    float a = r0[f], bb = r1[f];
                    vq[f] = a + (bb - a) * ty;
                }
            }
        }
        __syncthreads();

        // ---- Phase H: 2-tap horizontal lerp + epilogue ----
        if (!kodd) {
#pragma unroll
            for (int q4 = 0; q4 < 4; q4++) {
                const int p = t + q4 * 256;
                const int py = p >> 5, px = p & 31;
                const float* vq = VR + py * VPITCH - lo;
                const int c0 = COLI0[px], c1 = COLI1[px];
                const float tx = COLF[px];
                float* o = outb + (size_t)(y0 + py) * SC + (x0 + px) * C;
#pragma unroll
                for (int c = 0; c < C; c++) {
                    float a = vq[c0 + c], bb = vq[c1 + c];
                    float v = a + (bb - a) * tx;
                    __stcs(o + c, v * Ash[c] + Dsh[c]);
                }
            }
            return;
        } else {
#pragma unroll
            for (int q4 = 0; q4 < 4; q4++) {
                const int p = t + q4 * 256;
                const int py = p >> 5, px = p & 31;
                const float* vq = VR + px * VPITCH - lo;   // q-axis = px for k odd
                const int c0 = COLI0[py], c1 = COLI1[py];
                const float tx = COLF[py];
                float* d = OUTS + py * OPITCH + px * C;
#pragma unroll
                for (int c = 0; c < C; c++) {
                    float a = vq[c0 + c], bb = vq[c1 + c];
                    float v = a + (bb - a) * tx;
                    d[c] = v * Ash[c] + Dsh[c];
                }
            }
        }
    }

    // ---- writeback for k-odd paths (staged transposed results) ----
    __syncthreads();
#pragma unroll
    for (int q4 = 0; q4 < 4; q4++) {
        const int p = t + q4 * 256;
        const int py = p >> 5, px = p & 31;
        const float* s = OUTS + py * OPITCH + px * C;
        float* o = outb + (size_t)(y0 + py) * SC + (x0 + px) * C;
#pragma unroll
        for (int c = 0; c < C; c++)
            __stcs(o + c, s[c]);
    }
}

extern "C" void kernel_launch(void* const* d_in, const int* in_sizes, int n_in,
                              void* d_out, int out_size) {
    const float* crops     = (const float*)d_in[0];
    const float* off_frac  = (const float*)d_in[1];
    const float* bright    = (const float*)d_in[2];
    const float* contrast  = (const float*)d_in[3];
    const int*   crop_size = (const int*)d_in[4];
    const int*   do_crop   = (const int*)d_in[5];
    const int*   flip      = (const int*)d_in[6];
    const int*   rot_k     = (const int*)d_in[7];
    float*       out       = (float*)d_out;

    mean_kernel<<<dim3(B, SPLIT), 256>>>(crops, off_frac, crop_size, do_crop);
    aug_kernel<<<dim3(S / TX, S / TY, B), 256>>>(crops, off_frac, bright, contrast,
                                                 crop_size, do_crop, flip, rot_k, out);
}

// round 10
// speedup vs baseline: 1.2014x; 1.2014x over previous
#include <cuda_runtime.h>

#define S      256
#define C      5
#define SC     1280             // S*C floats per image row
#define B      64
#define SPLIT  8
#define TX     32
#define TY     32
#define PODD   161              // k-odd staging pitch (odd -> conflict-free scalar)
#define PEVEN  164              // k-even staging pitch (mult of 4 -> LDS.128)
#define OUTSZ  (32 * PEVEN)
#define GRAYW  (0.2989f + 0.5870f + 0.1140f)

// Per-(image,slab,channel) partial weighted sums. No device allocation allowed.
__device__ float g_part[B * SPLIT * C];

__device__ __forceinline__ void get_params(int b,
                                           const float* __restrict__ off_frac,
                                           const int* __restrict__ crop_size,
                                           const int* __restrict__ do_crop,
                                           bool& dc, float& scale, float& off0, float& off1) {
    dc = do_crop[b] != 0;
    float size_f = dc ? (float)crop_size[b] : (float)S;
    scale = size_f / (float)S;
    float span = (float)S - size_f + 1.0f;
    off0 = dc ? floorf(off_frac[2 * b + 0] * span) : 0.0f;
    off1 = dc ? floorf(off_frac[2 * b + 1] * span) : 0.0f;
}

__device__ __forceinline__ void inv_map(int k, bool fl, int y, int x, int& ry, int& rx) {
    switch (k) {
        case 0:  ry = y;         rx = x;         break;
        case 1:  ry = x;         rx = S - 1 - y; break;
        case 2:  ry = S - 1 - y; rx = S - 1 - x; break;
        default: ry = S - 1 - x; rx = y;         break;
    }
    if (fl) rx = S - 1 - rx;
}

// Per-pixel sample + fused epilogue, straight from gmem (L2-resident).
__device__ __forceinline__ void sample_px(
    const float* __restrict__ base, bool dc, float scale, float off0, float off1,
    int ry, int rx, const float* Ash, const float* Dsh, float v[C])
{
    if (!dc) {
        const float* s = base + (size_t)ry * SC + rx * C;
#pragma unroll
        for (int c = 0; c < C; c++) v[c] = s[c] * Ash[c] + Dsh[c];
        return;
    }
    const float cy = ((float)ry + 0.5f) * scale - 0.5f + off0;
    const float cx = ((float)rx + 0.5f) * scale - 0.5f + off1;
    const float fyf = floorf(cy), fxf = floorf(cx);
    const int i0 = min(max((int)fyf, 0), S - 1);
    const int i1 = min(max((int)fyf + 1, 0), S - 1);
    const int j0 = min(max((int)fxf, 0), S - 1);
    const int j1 = min(max((int)fxf + 1, 0), S - 1);
    const float ty = cy - fyf;
    const float tx = cx - fxf;

    const float* r0 = base + (size_t)i0 * SC;
    const float* r1 = base + (size_t)i1 * SC;
    const int c0 = j0 * C, c1 = j1 * C;
#pragma unroll
    for (int c = 0; c < C; c++) {
        float p00 = r0[c0 + c], p01 = r0[c1 + c];
        float p10 = r1[c0 + c], p11 = r1[c1 + c];
        float a  = p00 + (p10 - p00) * ty;
        float bb = p01 + (p11 - p01) * ty;
        float vv = a + (bb - a) * tx;
        v[c] = vv * Ash[c] + Dsh[c];
    }
}

// ---------------------------------------------------------------------------
// K1: per-(b,slab,c) partial weighted mean of the resampled image (~LTS cap).
// ---------------------------------------------------------------------------
__global__ __launch_bounds__(256) void mean_kernel(
    const float* __restrict__ img,
    const float* __restrict__ off_frac,
    const int* __restrict__ crop_size,
    const int* __restrict__ do_crop)
{
    __shared__ float W0[S];
    __shared__ float W1[S];
    __shared__ float red[8][C];

    const int b = blockIdx.x;
    const int slab = blockIdx.y;
    const int t = threadIdx.x;

    bool dc; float scale, off0, off1;
    get_params(b, off_frac, crop_size, do_crop, dc, scale, off0, off1);

    W0[t] = 0.0f;
    W1[t] = 0.0f;
    __syncthreads();

    {
        float base = ((float)t + 0.5f) * scale - 0.5f;

        float c0 = base + off0;
        float f0 = floorf(c0);
        int  i0 = min(max((int)f0, 0), S - 1);
        int  i1 = min(max((int)f0 + 1, 0), S - 1);
        float fy = c0 - f0;
        atomicAdd(&W0[i0], 1.0f - fy);
        atomicAdd(&W0[i1], fy);

        float c1 = base + off1;
        float f1 = floorf(c1);
        int  j0 = min(max((int)f1, 0), S - 1);
        int  j1 = min(max((int)f1 + 1, 0), S - 1);
        float fx = c1 - f1;
        atomicAdd(&W1[j0], 1.0f - fx);
        atomicAdd(&W1[j1], fx);
    }
    __syncthreads();

    const int g = t & 63;          // pixel group (4 px)
    const int r = t >> 6;          // row lane 0..3
    const int px0 = g * 4;
    float w1v0 = W1[px0], w1v1 = W1[px0 + 1], w1v2 = W1[px0 + 2], w1v3 = W1[px0 + 3];

    float acc[C] = {0.f, 0.f, 0.f, 0.f, 0.f};
    const int rows = S / SPLIT;
    const int row0 = slab * rows;
    const float* base = img + (size_t)b * S * SC;

    for (int it = 0; it < rows / 4; it++) {
        const int i = row0 + r + it * 4;
        const float w0 = W0[i];
        if (w0 == 0.0f) continue;
        const float4* p4 = (const float4*)(base + (size_t)i * SC + px0 * C);
        float4 v0 = p4[0], v1 = p4[1], v2 = p4[2], v3 = p4[3], v4 = p4[4];
        float ww0 = w0 * w1v0, ww1 = w0 * w1v1, ww2 = w0 * w1v2, ww3 = w0 * w1v3;
        acc[0] += v0.x * ww0; acc[1] += v0.y * ww0; acc[2] += v0.z * ww0; acc[3] += v0.w * ww0;
        acc[4] += v1.x * ww0;
        acc[0] += v1.y * ww1; acc[1] += v1.z * ww1; acc[2] += v1.w * ww1;
        acc[3] += v2.x * ww1; acc[4] += v2.y * ww1;
        acc[0] += v2.z * ww2; acc[1] += v2.w * ww2; acc[2] += v3.x * ww2;
        acc[3] += v3.y * ww2; acc[4] += v3.z * ww2;
        acc[0] += v3.w * ww3; acc[1] += v4.x * ww3; acc[2] += v4.y * ww3;
        acc[3] += v4.z * ww3; acc[4] += v4.w * ww3;
    }

#pragma unroll
    for (int c = 0; c < C; c++) {
        float v = acc[c];
#pragma unroll
        for (int o = 16; o > 0; o >>= 1)
            v += __shfl_down_sync(0xffffffffu, v, o);
        if ((t & 31) == 0) red[t >> 5][c] = v;
    }
    __syncthreads();

    if (t < C) {
        float s = 0.f;
#pragma unroll
        for (int w = 0; w < 8; w++) s += red[w][t];
        g_part[(b * SPLIT + slab) * C + t] = s;
    }
}

// ---------------------------------------------------------------------------
// K2: R5 direct-gather skeleton + vectorized k-even I/O.
//  A) no-crop, k even : 4px/thread pure LDG.128 -> STG.128 (no smem/barrier)
//  B) k odd (any)     : warp-per-column gather -> OUT(161) -> scalar writeback
//  C) crop,  k even   : per-pixel 4-tap gmem gather (full MLP) -> OUT(164)
//                       -> LDS.128/STG.128 writeback
// Block = 32x32 tile; grid (8, 8, B); 256 threads, 4 px/thread.
// ---------------------------------------------------------------------------
__global__ __launch_bounds__(256) void aug_kernel(
    const float* __restrict__ img,
    const float* __restrict__ off_frac,
    const float* __restrict__ bright,
    const float* __restrict__ contrast,
    const int* __restrict__ crop_size,
    const int* __restrict__ do_crop,
    const int* __restrict__ flip,
    const int* __restrict__ rot_k,
    float* __restrict__ out)
{
    __shared__ float OUTS[OUTSZ];
    __shared__ float Ash[C], Dsh[C];

    const int b  = blockIdx.z;
    const int x0 = blockIdx.x * TX;
    const int y0 = blockIdx.y * TY;
    const int t  = threadIdx.x;

    bool dc; float scale, off0, off1;
    get_params(b, off_frac, crop_size, do_crop, dc, scale, off0, off1);
    const int k = rot_k[b] & 3;
    const bool fl = flip[b] != 0;
    const int kodd = k & 1;

    if (t < C) {
        const float inv_area = 1.0f / (float)(S * S);
        float s = 0.f;
#pragma unroll
        for (int p = 0; p < SPLIT; p++) s += g_part[(b * SPLIT + p) * C + t];
        float m = s * inv_area;
        float cc = contrast[b * C + t];
        Ash[t] = cc * GRAYW;
        Dsh[t] = (m * (1.0f - cc) + bright[b * C + t]) * GRAYW;
    }
    __syncthreads();

    const float* imgb = img + (size_t)b * S * SC;
    float* outb = out + (size_t)b * S * SC;

    if (!dc && !kodd) {
        // ---- A: exact-pixel row copy, fully vectorized ----
        const int py = t >> 3, g = t & 7;
        const int y = y0 + py, xg = x0 + g * 4;
        int ry, rxA, rxB, d0;
        inv_map(k, fl, y, xg, ry, rxA);
        inv_map(k, fl, y, xg + 1, d0, rxB);
        const bool rev = rxB < rxA;
        const int jf = (rev ? rxA - 3 : rxA) * C;          // 16B-aligned
        const float4* src = (const float4*)(imgb + (size_t)ry * SC + jf);
        float4 w0 = src[0], w1 = src[1], w2 = src[2], w3 = src[3], w4 = src[4];
        float v[20] = {w0.x, w0.y, w0.z, w0.w, w1.x, w1.y, w1.z, w1.w,
                       w2.x, w2.y, w2.z, w2.w, w3.x, w3.y, w3.z, w3.w,
                       w4.x, w4.y, w4.z, w4.w};
        float r[20];
        if (rev) {
#pragma unroll
            for (int p = 0; p < 4; p++)
#pragma unroll
                for (int c = 0; c < C; c++)
                    r[p * C + c] = v[(3 - p) * C + c] * Ash[c] + Dsh[c];
        } else {
#pragma unroll
            for (int p = 0; p < 4; p++)
#pragma unroll
                for (int c = 0; c < C; c++)
                    r[p * C + c] = v[p * C + c] * Ash[c] + Dsh[c];
        }
        float4* o = (float4*)(outb + (size_t)y * SC + xg * C);
        __stcs(o + 0, make_float4(r[0],  r[1],  r[2],  r[3]));
        __stcs(o + 1, make_float4(r[4],  r[5],  r[6],  r[7]));
        __stcs(o + 2, make_float4(r[8],  r[9],  r[10], r[11]));
        __stcs(o + 3, make_float4(r[12], r[13], r[14], r[15]));
        __stcs(o + 4, make_float4(r[16], r[17], r[18], r[19]));
        return;
    }

    if (kodd) {
        // ---- B: warp per output column (coalesced gather), scalar staging ----
        const int w = t >> 5, l = t & 31;
#pragma unroll
        for (int q = 0; q < 4; q++) {
            const int xl = w + q * 8;
            const int x = x0 + xl;
            const int y = y0 + l;
            int ry, rx;
            inv_map(k, fl, y, x, ry, rx);
            float v[C];
            sample_px(imgb, dc, scale, off0, off1, ry, rx, Ash, Dsh, v);
            float* s = OUTS + l * PODD + xl * C;
#pragma unroll
            for (int c = 0; c < C; c++) s[c] = v[c];
        }
        __syncthreads();
#pragma unroll
        for (int q = 0; q < 4; q++) {
            const int p  = t + q * 256;
            const int py = p >> 5;
            const int px = p & 31;
            const float* s = OUTS + py * PODD + px * C;
            float* o = outb + (size_t)(y0 + py) * SC + (x0 + px) * C;
#pragma unroll
            for (int c = 0; c < C; c++) o[c] = s[c];
        }
    } else {
        // ---- C: crop, k even: direct 4-tap gather (full MLP), vector writeback ----
#pragma unroll
        for (int q = 0; q < 4; q++) {
            const int p  = t + q * 256;
            const int py = p >> 5;
            const int px = p & 31;
            int ry, rx;
            inv_map(k, fl, y0 + py, x0 + px, ry, rx);
            float v[C];
            sample_px(imgb, dc, scale, off0, off1, ry, rx, Ash, Dsh, v);
            float* s = OUTS + py * PEVEN + px * C;      // lane-stride 5: conflict-free
#pragma unroll
            for (int c = 0; c < C; c++) s[c] = v[c];
        }
        __syncthreads();
        float* outbase = outb + (size_t)y0 * SC + x0 * C;
        for (int j = t; j < TY * (TX * C / 4); j += 256) {   // 1280 float4s, 5 iters
            const int row  = j / 40;
            const int col4 = j - row * 40;
            float4 v = *(const float4*)(OUTS + row * PEVEN + col4 * 4);
            __stcs((float4*)(outbase + (size_t)row * SC + col4 * 4), v);
        }
    }
}

extern "C" void kernel_launch(void* const* d_in, const int* in_sizes, int n_in,
                              void* d_out, int out_size) {
    const float* crops     = (const float*)d_in[0];
    const float* off_frac  = (const float*)d_in[1];
    const float* bright    = (const float*)d_in[2];
    const float* contrast  = (const float*)d_in[3];
    const int*   crop_size = (const int*)d_in[4];
    const int*   do_crop   = (const int*)d_in[5];
    const int*   flip      = (const int*)d_in[6];
    const int*   rot_k     = (const int*)d_in[7];
    float*       out       = (float*)d_out;

    mean_kernel<<<dim3(B, SPLIT), 256>>>(crops, off_frac, crop_size, do_crop);
    aug_kernel<<<dim3(S / TX, S / TY, B), 256>>>(crops, off_frac, bright, contrast,
                                                 crop_size, do_crop, flip, rot_k, out);
}

// round 11
// speedup vs baseline: 1.3422x; 1.1171x over previous
#include <cuda_runtime.h>

#define S      256
#define C      5
#define SC     1280             // S*C floats per image row
#define B      64
#define SPLIT  8
#define TX     32
#define TY     16
#define THR    128
#define PODD   161              // k-odd staging pitch (odd -> conflict-free scalar)
#define PEVEN  164              // k-even staging pitch (mult of 4 -> LDS.128)
#define OUTSZ  (TY * PEVEN)
#define GRAYW  (0.2989f + 0.5870f + 0.1140f)

// Per-(image,slab,channel) partial weighted sums. No device allocation allowed.
__device__ float g_part[B * SPLIT * C];

__device__ __forceinline__ void get_params(int b,
                                           const float* __restrict__ off_frac,
                                           const int* __restrict__ crop_size,
                                           const int* __restrict__ do_crop,
                                           bool& dc, float& scale, float& off0, float& off1) {
    dc = do_crop[b] != 0;
    float size_f = dc ? (float)crop_size[b] : (float)S;
    scale = size_f / (float)S;
    float span = (float)S - size_f + 1.0f;
    off0 = dc ? floorf(off_frac[2 * b + 0] * span) : 0.0f;
    off1 = dc ? floorf(off_frac[2 * b + 1] * span) : 0.0f;
}

__device__ __forceinline__ void inv_map(int k, bool fl, int y, int x, int& ry, int& rx) {
    switch (k) {
        case 0:  ry = y;         rx = x;         break;
        case 1:  ry = x;         rx = S - 1 - y; break;
        case 2:  ry = S - 1 - y; rx = S - 1 - x; break;
        default: ry = S - 1 - x; rx = y;         break;
    }
    if (fl) rx = S - 1 - rx;
}

// Per-pixel sample + fused epilogue, straight from gmem (L2-resident).
__device__ __forceinline__ void sample_px(
    const float* __restrict__ base, bool dc, float scale, float off0, float off1,
    int ry, int rx, const float* Ash, const float* Dsh, float v[C])
{
    if (!dc) {
        const float* s = base + (size_t)ry * SC + rx * C;
#pragma unroll
        for (int c = 0; c < C; c++) v[c] = s[c] * Ash[c] + Dsh[c];
        return;
    }
    const float cy = ((float)ry + 0.5f) * scale - 0.5f + off0;
    const float cx = ((float)rx + 0.5f) * scale - 0.5f + off1;
    const float fyf = floorf(cy), fxf = floorf(cx);
    const int i0 = min(max((int)fyf, 0), S - 1);
    const int i1 = min(max((int)fyf + 1, 0), S - 1);
    const int j0 = min(max((int)fxf, 0), S - 1);
    const int j1 = min(max((int)fxf + 1, 0), S - 1);
    const float ty = cy - fyf;
    const float tx = cx - fxf;

    const float* r0 = base + (size_t)i0 * SC;
    const float* r1 = base + (size_t)i1 * SC;
    const int c0 = j0 * C, c1 = j1 * C;
#pragma unroll
    for (int c = 0; c < C; c++) {
        float p00 = r0[c0 + c], p01 = r0[c1 + c];
        float p10 = r1[c0 + c], p11 = r1[c1 + c];
        float a  = p00 + (p10 - p00) * ty;
        float bb = p01 + (p11 - p01) * ty;
        float vv = a + (bb - a) * tx;
        v[c] = vv * Ash[c] + Dsh[c];
    }
}

// ---------------------------------------------------------------------------
// K1: per-(b,slab,c) partial weighted mean of the resampled image (~LTS cap).
// ---------------------------------------------------------------------------
__global__ __launch_bounds__(256) void mean_kernel(
    const float* __restrict__ img,
    const float* __restrict__ off_frac,
    const int* __restrict__ crop_size,
    const int* __restrict__ do_crop)
{
    __shared__ float W0[S];
    __shared__ float W1[S];
    __shared__ float red[8][C];

    const int b = blockIdx.x;
    const int slab = blockIdx.y;
    const int t = threadIdx.x;

    bool dc; float scale, off0, off1;
    get_params(b, off_frac, crop_size, do_crop, dc, scale, off0, off1);

    W0[t] = 0.0f;
    W1[t] = 0.0f;
    __syncthreads();

    {
        float base = ((float)t + 0.5f) * scale - 0.5f;

        float c0 = base + off0;
        float f0 = floorf(c0);
        int  i0 = min(max((int)f0, 0), S - 1);
        int  i1 = min(max((int)f0 + 1, 0), S - 1);
        float fy = c0 - f0;
        atomicAdd(&W0[i0], 1.0f - fy);
        atomicAdd(&W0[i1], fy);

        float c1 = base + off1;
        float f1 = floorf(c1);
        int  j0 = min(max((int)f1, 0), S - 1);
        int  j1 = min(max((int)f1 + 1, 0), S - 1);
        float fx = c1 - f1;
        atomicAdd(&W1[j0], 1.0f - fx);
        atomicAdd(&W1[j1], fx);
    }
    __syncthreads();

    const int g = t & 63;          // pixel group (4 px)
    const int r = t >> 6;          // row lane 0..3
    const int px0 = g * 4;
    float w1v0 = W1[px0], w1v1 = W1[px0 + 1], w1v2 = W1[px0 + 2], w1v3 = W1[px0 + 3];

    float acc[C] = {0.f, 0.f, 0.f, 0.f, 0.f};
    const int rows = S / SPLIT;
    const int row0 = slab * rows;
    const float* base = img + (size_t)b * S * SC;

    for (int it = 0; it < rows / 4; it++) {
        const int i = row0 + r + it * 4;
        const float w0 = W0[i];
        if (w0 == 0.0f) continue;
        const float4* p4 = (const float4*)(base + (size_t)i * SC + px0 * C);
        float4 v0 = p4[0], v1 = p4[1], v2 = p4[2], v3 = p4[3], v4 = p4[4];
        float ww0 = w0 * w1v0, ww1 = w0 * w1v1, ww2 = w0 * w1v2, ww3 = w0 * w1v3;
        acc[0] += v0.x * ww0; acc[1] += v0.y * ww0; acc[2] += v0.z * ww0; acc[3] += v0.w * ww0;
        acc[4] += v1.x * ww0;
        acc[0] += v1.y * ww1; acc[1] += v1.z * ww1; acc[2] += v1.w * ww1;
        acc[3] += v2.x * ww1; acc[4] += v2.y * ww1;
        acc[0] += v2.z * ww2; acc[1] += v2.w * ww2; acc[2] += v3.x * ww2;
        acc[3] += v3.y * ww2; acc[4] += v3.z * ww2;
        acc[0] += v3.w * ww3; acc[1] += v4.x * ww3; acc[2] += v4.y * ww3;
        acc[3] += v4.z * ww3; acc[4] += v4.w * ww3;
    }

#pragma unroll
    for (int c = 0; c < C; c++) {
        float v = acc[c];
#pragma unroll
        for (int o = 16; o > 0; o >>= 1)
            v += __shfl_down_sync(0xffffffffu, v, o);
        if ((t & 31) == 0) red[t >> 5][c] = v;
    }
    __syncthreads();

    if (t < C) {
        float s = 0.f;
#pragma unroll
        for (int w = 0; w < 8; w++) s += red[w][t];
        g_part[(b * SPLIT + slab) * C + t] = s;
    }
}

// ---------------------------------------------------------------------------
// K2: direct-gather skeleton, 128-thread blocks for 12 blocks/SM occupancy.
//  A) no-crop, k even : 4px/thread pure LDG.128 -> STG.128 (no smem/barrier)
//  B) k odd (any)     : half-warp-per-column gather -> OUT(161) -> writeback
//  C) crop,  k even   : per-pixel 4-tap gmem gather (full MLP) -> OUT(164)
//                       -> LDS.128/STG.128 writeback
// Block = 32x16 tile; grid (8, 16, B); 128 threads, 4 px/thread.
// ---------------------------------------------------------------------------
__global__ __launch_bounds__(THR, 12) void aug_kernel(
    const float* __restrict__ img,
    const float* __restrict__ off_frac,
    const float* __restrict__ bright,
    const float* __restrict__ contrast,
    const int* __restrict__ crop_size,
    const int* __restrict__ do_crop,
    const int* __restrict__ flip,
    const int* __restrict__ rot_k,
    float* __restrict__ out)
{
    __shared__ float OUTS[OUTSZ];
    __shared__ float Ash[C], Dsh[C];

    const int b  = blockIdx.z;
    const int x0 = blockIdx.x * TX;
    const int y0 = blockIdx.y * TY;
    const int t  = threadIdx.x;

    bool dc; float scale, off0, off1;
    get_params(b, off_frac, crop_size, do_crop, dc, scale, off0, off1);
    const int k = rot_k[b] & 3;
    const bool fl = flip[b] != 0;
    const int kodd = k & 1;

    if (t < C) {
        const float inv_area = 1.0f / (float)(S * S);
        float s = 0.f;
#pragma unroll
        for (int p = 0; p < SPLIT; p++) s += g_part[(b * SPLIT + p) * C + t];
        float m = s * inv_area;
        float cc = contrast[b * C + t];
        Ash[t] = cc * GRAYW;
        Dsh[t] = (m * (1.0f - cc) + bright[b * C + t]) * GRAYW;
    }
    __syncthreads();

    const float* imgb = img + (size_t)b * S * SC;
    float* outb = out + (size_t)b * S * SC;

    if (!dc && !kodd) {
        // ---- A: exact-pixel row copy, fully vectorized (4 px/thread) ----
        const int py = t >> 3, g = t & 7;
        const int y = y0 + py, xg = x0 + g * 4;
        int ry, rxA, rxB, d0;
        inv_map(k, fl, y, xg, ry, rxA);
        inv_map(k, fl, y, xg + 1, d0, rxB);
        const bool rev = rxB < rxA;
        const int jf = (rev ? rxA - 3 : rxA) * C;          // 16B-aligned
        const float4* src = (const float4*)(imgb + (size_t)ry * SC + jf);
        float4 w0 = src[0], w1 = src[1], w2 = src[2], w3 = src[3], w4 = src[4];
        float v[20] = {w0.x, w0.y, w0.z, w0.w, w1.x, w1.y, w1.z, w1.w,
                       w2.x, w2.y, w2.z, w2.w, w3.x, w3.y, w3.z, w3.w,
                       w4.x, w4.y, w4.z, w4.w};
        float r[20];
        if (rev) {
#pragma unroll
            for (int p = 0; p < 4; p++)
#pragma unroll
                for (int c = 0; c < C; c++)
                    r[p * C + c] = v[(3 - p) * C + c] * Ash[c] + Dsh[c];
        } else {
#pragma unroll
            for (int p = 0; p < 4; p++)
#pragma unroll
                for (int c = 0; c < C; c++)
                    r[p * C + c] = v[p * C + c] * Ash[c] + Dsh[c];
        }
        float4* o = (float4*)(outb + (size_t)y * SC + xg * C);
        __stcs(o + 0, make_float4(r[0],  r[1],  r[2],  r[3]));
        __stcs(o + 1, make_float4(r[4],  r[5],  r[6],  r[7]));
        __stcs(o + 2, make_float4(r[8],  r[9],  r[10], r[11]));
        __stcs(o + 3, make_float4(r[12], r[13], r[14], r[15]));
        __stcs(o + 4, make_float4(r[16], r[17], r[18], r[19]));
        return;
    }

    if (kodd) {
        // ---- B: half-warp per output column (coalesced gather), staging ----
        const int w = t >> 5, l = t & 31;
        const int ly = l & 15;              // y within tile
        const int half = l >> 4;            // 0/1: which of the column pair
#pragma unroll
        for (int q = 0; q < 4; q++) {
            const int xl = (w + q * 4) * 2 + half;   // 0..31
            const int x = x0 + xl;
            const int y = y0 + ly;
            int ry, rx;
            inv_map(k, fl, y, x, ry, rx);
            float v[C];
            sample_px(imgb, dc, scale, off0, off1, ry, rx, Ash, Dsh, v);
            float* s = OUTS + ly * PODD + xl * C;
#pragma unroll
            for (int c = 0; c < C; c++) s[c] = v[c];
        }
        __syncthreads();
#pragma unroll
        for (int q = 0; q < 4; q++) {
            const int p  = t + q * THR;
            const int py = p >> 5;
            const int px = p & 31;
            const float* s = OUTS + py * PODD + px * C;
            float* o = outb + (size_t)(y0 + py) * SC + (x0 + px) * C;
#pragma unroll
            for (int c = 0; c < C; c++) o[c] = s[c];
        }
    } else {
        // ---- C: crop, k even: direct 4-tap gather (full MLP), vector writeback ----
#pragma unroll
        for (int q = 0; q < 4; q++) {
            const int p  = t + q * THR;
            const int py = p >> 5;
            const int px = p & 31;
            int ry, rx;
            inv_map(k, fl, y0 + py, x0 + px, ry, rx);
            float v[C];
            sample_px(imgb, dc, scale, off0, off1, ry, rx, Ash, Dsh, v);
            float* s = OUTS + py * PEVEN + px * C;      // lane-stride 5: conflict-free
#pragma unroll
            for (int c = 0; c < C; c++) s[c] = v[c];
        }
        __syncthreads();
        float* outbase = outb + (size_t)y0 * SC + x0 * C;
        for (int j = t; j < TY * (TX * C / 4); j += THR) {   // 640 float4s, 5 iters
            const int row  = j / 40;
            const int col4 = j - row * 40;
            float4 v = *(const float4*)(OUTS + row * PEVEN + col4 * 4);
            __stcs((float4*)(outbase + (size_t)row * SC + col4 * 4), v);
        }
    }
}

extern "C" void kernel_launch(void* const* d_in, const int* in_sizes, int n_in,
                              void* d_out, int out_size) {
    const float* crops     = (const float*)d_in[0];
    const float* off_frac  = (const float*)d_in[1];
    const float* bright    = (const float*)d_in[2];
    const float* contrast  = (const float*)d_in[3];
    const int*   crop_size = (const int*)d_in[4];
    const int*   do_crop   = (const int*)d_in[5];
    const int*   flip      = (const int*)d_in[6];
    const int*   rot_k     = (const int*)d_in[7];
    float*       out       = (float*)d_out;

    mean_kernel<<<dim3(B, SPLIT), 256>>>(crops, off_frac, crop_size, do_crop);
    aug_kernel<<<dim3(S / TX, S / TY, B), THR>>>(crops, off_frac, bright, contrast,
                                                 crop_size, do_crop, flip, rot_k, out);
}